// round 10
// baseline (speedup 1.0000x reference)
#include <cuda_runtime.h>

#define IMW 1024
#define IMH 1024
#define HW  (IMW * IMH)
#define TW 16
#define TH 64
#define HALO_W 22
#define HALO_H 70
#define SSTRIDE 24
#define CH_STRIDE (HALO_H * SSTRIDE)    // 1680 floats per channel
#define F_WORDS (11 * CH_STRIDE)        // 18480 -> 73,920 B smem
#define EPSR 1e-4f
#define SGN2 0x8000000080000000ULL
#define NPROWS (IMH / 2)                // 512 pair-rows

typedef unsigned long long ull;

// scratch: [pairRow][moment][x]  (512 * 60 * 1024 ull = 251.7 MB)
__device__ ull g_scratch[(size_t)NPROWS * 60 * IMW];

// ---- packed f32x2 helpers -------------------------------------------------
__device__ __forceinline__ ull pk2(float lo, float hi) {
    ull r;
    asm("mov.b64 %0, {%1, %2};" : "=l"(r) : "f"(lo), "f"(hi));
    return r;
}
__device__ __forceinline__ void ffma2(ull& d, ull a, ull b) {
    asm("fma.rn.f32x2 %0, %1, %2, %0;" : "+l"(d) : "l"(a), "l"(b));
}
__device__ __forceinline__ ull ffma2g(ull a, ull b, ull c) {
    ull r;
    asm("fma.rn.f32x2 %0, %1, %2, %3;" : "=l"(r) : "l"(a), "l"(b), "l"(c));
    return r;
}
__device__ __forceinline__ ull mul2(ull a, ull b) {
    ull r;
    asm("mul.rn.f32x2 %0, %1, %2;" : "=l"(r) : "l"(a), "l"(b));
    return r;
}
__device__ __forceinline__ ull add2(ull a, ull b) {
    ull r;
    asm("add.rn.f32x2 %0, %1, %2;" : "=l"(r) : "l"(a), "l"(b));
    return r;
}
__device__ __forceinline__ void upk2(ull v, float& lo, float& hi) {
    asm("mov.b64 {%0, %1}, %2;" : "=f"(lo), "=f"(hi) : "l"(v));
}
__device__ __forceinline__ float frcp(float x) {
    float r;
    asm("rcp.approx.f32 %0, %1;" : "=f"(r) : "f"(x));
    return r;
}
__host__ __device__ constexpr int IDX(int i, int j) {  // upper-tri 8x8, i<=j
    return i * 8 - i * (i - 1) / 2 + (j - i);
}

// 7 horizontal taps at one row-pair base; SUB subtracts (sign-flip 1st operand)
template<bool SUB>
__device__ __forceinline__ void tap7(const float* __restrict__ rp, ull A[60]) {
#pragma unroll
    for (int dx = 0; dx < 7; ++dx) {
        ull v[11];
#pragma unroll
        for (int ch = 0; ch < 11; ++ch)
            v[ch] = pk2(rp[ch * CH_STRIDE + dx],
                        rp[ch * CH_STRIDE + dx + SSTRIDE]);
        int k = 0;
#pragma unroll
        for (int i = 0; i < 8; ++i) {
            const ull si = SUB ? (v[i] ^ SGN2) : v[i];
#pragma unroll
            for (int j = i; j < 8; ++j) { ffma2(A[k], si, v[j]); ++k; }
#pragma unroll
            for (int c = 0; c < 3; ++c) ffma2(A[36 + i * 3 + c], si, v[8 + c]);
        }
    }
}

// ======================= kernel A: windowed moments =========================
__global__ __launch_bounds__(128)
void moments_kernel(const float* __restrict__ inp,
                    const float* __restrict__ dep,
                    const float* __restrict__ alb,
                    const float* __restrict__ nrm)
{
    extern __shared__ float S[];        // S[ch][r][c], stride 24

    const int tid = threadIdx.x;
    const int bx = blockIdx.x, by = blockIdx.y;
    const int gx0 = bx * TW - 3;
    const int gy0 = by * TH - 3;

    // ---- stage halo features (zeros outside image) ----
    for (int idx = tid; idx < HALO_H * HALO_W; idx += 128) {
        const int r = idx / HALO_W;
        const int c = idx - r * HALO_W;
        const int gy = gy0 + r;
        const int gx = gx0 + c;
        float v[11];
        if ((unsigned)gy < (unsigned)IMH && (unsigned)gx < (unsigned)IMW) {
            const int g = gy * IMW + gx;
            v[0] = 1.0f;
            v[1] = dep[g];
            v[2] = alb[g];  v[3] = alb[g + HW];  v[4] = alb[g + 2 * HW];
            v[5] = nrm[g];  v[6] = nrm[g + HW];  v[7] = nrm[g + 2 * HW];
            v[8] = inp[g];  v[9] = inp[g + HW];  v[10] = inp[g + 2 * HW];
        } else {
#pragma unroll
            for (int ch = 0; ch < 11; ++ch) v[ch] = 0.0f;
        }
#pragma unroll
        for (int ch = 0; ch < 11; ++ch)
            S[ch * CH_STRIDE + r * SSTRIDE + c] = v[ch];
    }
    __syncthreads();

    const int lx = tid & 15;
    const int ty = tid >> 4;                // 0..7
    const int lp0 = 8 * ty;                 // first local output row
    const int x = bx * TW + lx;

    ull A[60];
#pragma unroll
    for (int m = 0; m < 60; ++m) A[m] = 0ULL;

    // prologue: pair 0 = full 49 taps
    {
        const float* b = &S[lp0 * SSTRIDE + lx];
#pragma unroll
        for (int dy = 0; dy < 7; ++dy)
            tap7<false>(b + dy * SSTRIDE, A);
    }

#pragma unroll 1
    for (int k = 0; k < 4; ++k) {
        const int lp = lp0 + 2 * k;
        if (k > 0) {
            const float* b = &S[lp * SSTRIDE + lx];
            tap7<false>(b + 5 * SSTRIDE, A);
            tap7<false>(b + 6 * SSTRIDE, A);
            tap7<true >(b - 2 * SSTRIDE, A);
            tap7<true >(b - 1 * SSTRIDE, A);
        }
        // write out: pairRow = by*32 + ty*4 + k
        const int py = by * (TH / 2) + ty * 4 + k;
        ull* wp = g_scratch + (size_t)py * 60 * IMW + x;
#pragma unroll
        for (int m = 0; m < 60; ++m) wp[(size_t)m * IMW] = A[m];
    }
}

// ======================= kernel B: per-pair solves ==========================
__global__ __launch_bounds__(256)
void solve_kernel(const float* __restrict__ inp,
                  const float* __restrict__ dep,
                  const float* __restrict__ alb,
                  const float* __restrict__ nrm,
                  float* __restrict__ out)
{
    const int x = blockIdx.x * 256 + threadIdx.x;
    const int py = blockIdx.y;
    const ull* rp = g_scratch + (size_t)py * 60 * IMW + x;

    // load AtA upper triangle
    ull w[36];
#pragma unroll
    for (int m = 0; m < 36; ++m) w[m] = rp[(size_t)m * IMW];

    const ull EPS2 = pk2(EPSR, EPSR);
#pragma unroll
    for (int i = 0; i < 8; ++i) w[IDX(i, i)] = add2(w[IDX(i, i)], EPS2);

    // RHS = center-pixel features for rows (2py, 2py+1)
    ull rhs[8];
    {
        const int g = (2 * py) * IMW + x;
        rhs[0] = pk2(1.0f, 1.0f);
        rhs[1] = pk2(dep[g], dep[g + IMW]);
        rhs[2] = pk2(alb[g], alb[g + IMW]);
        rhs[3] = pk2(alb[g + HW], alb[g + HW + IMW]);
        rhs[4] = pk2(alb[g + 2 * HW], alb[g + 2 * HW + IMW]);
        rhs[5] = pk2(nrm[g], nrm[g + IMW]);
        rhs[6] = pk2(nrm[g + HW], nrm[g + HW + IMW]);
        rhs[7] = pk2(nrm[g + 2 * HW], nrm[g + 2 * HW + IMW]);
    }

    // symmetric Gaussian elimination (SPD + Tikhonov; no pivoting)
#pragma unroll
    for (int k = 0; k < 8; ++k) {
        float dlo, dhi;
        upk2(w[IDX(k, k)], dlo, dhi);
        const ull ninv = pk2(-frcp(dlo), -frcp(dhi));
#pragma unroll
        for (int i = k + 1; i < 8; ++i) {
            const ull li = mul2(w[IDX(k, i)], ninv);     // -a_ki / d_k
            rhs[i] = ffma2g(li, rhs[k], rhs[i]);
#pragma unroll
            for (int j = i; j < 8; ++j)
                w[IDX(i, j)] = ffma2g(li, w[IDX(k, j)], w[IDX(i, j)]);
        }
    }
    ull nx[8];
#pragma unroll
    for (int i = 7; i >= 0; --i) {
        ull s = rhs[i];
#pragma unroll
        for (int j = 7; j > i; --j)
            s = ffma2g(w[IDX(i, j)], nx[j], s);
        float dlo, dhi;
        upk2(w[IDX(i, i)], dlo, dhi);
        nx[i] = mul2(s, pk2(-frcp(dlo), -frcp(dhi)));
    }

    // out_c = x . AtY_c = -(nx . AtY_c); AtY loaded here (not during solve)
    const int go = (2 * py) * IMW + x;
#pragma unroll
    for (int c = 0; c < 3; ++c) {
        ull a2 = 0ULL;
#pragma unroll
        for (int i = 0; i < 8; ++i)
            ffma2(a2, nx[i], rp[(size_t)(36 + i * 3 + c) * IMW]);
        float olo, ohi;
        upk2(a2, olo, ohi);
        out[c * HW + go]       = -olo;
        out[c * HW + go + IMW] = -ohi;
    }
}

extern "C" void kernel_launch(void* const* d_in, const int* in_sizes, int n_in,
                              void* d_out, int out_size) {
    const float* inp   = (const float*)d_in[0];
    const float* depth = (const float*)d_in[1];
    const float* alb   = (const float*)d_in[2];
    const float* nrm   = (const float*)d_in[3];
    float* out = (float*)d_out;

    cudaFuncSetAttribute(moments_kernel,
                         cudaFuncAttributeMaxDynamicSharedMemorySize,
                         F_WORDS * 4);
    dim3 gridA(IMW / TW, IMH / TH);       // (64, 16)
    moments_kernel<<<gridA, 128, F_WORDS * 4>>>(inp, depth, alb, nrm);

    dim3 gridB(IMW / 256, NPROWS);        // (4, 512)
    solve_kernel<<<gridB, 256>>>(inp, depth, alb, nrm, out);
}

// round 11
// speedup vs baseline: 1.2018x; 1.2018x over previous
#include <cuda_runtime.h>

#define IMW 1024
#define IMH 1024
#define HW  (IMW * IMH)
#define TW 16
#define TH 32
#define HALO_W 22
#define HALO_H 38
#define SSTRIDE 22
#define CH_STRIDE (HALO_H * SSTRIDE)    // 836 floats per channel
#define F_WORDS (11 * CH_STRIDE)        // 9196 floats = 36,784 B
#define XSTR 61                          // stash stride (ull): conflict-free
#define X_ULL (128 * XSTR)               // 7808 ull = 62,464 B
#define SMEM_BYTES (F_WORDS * 4 + X_ULL * 8)   // 99,248 B -> 2 CTAs/SM
#define EPSR 1e-4f
#define SGN2 0x8000000080000000ULL

typedef unsigned long long ull;

// ---- packed f32x2 helpers -------------------------------------------------
__device__ __forceinline__ ull pk2(float lo, float hi) {
    ull r;
    asm("mov.b64 %0, {%1, %2};" : "=l"(r) : "f"(lo), "f"(hi));
    return r;
}
__device__ __forceinline__ void ffma2(ull& d, ull a, ull b) {
    asm("fma.rn.f32x2 %0, %1, %2, %0;" : "+l"(d) : "l"(a), "l"(b));
}
__device__ __forceinline__ ull ffma2g(ull a, ull b, ull c) {
    ull r;
    asm("fma.rn.f32x2 %0, %1, %2, %3;" : "=l"(r) : "l"(a), "l"(b), "l"(c));
    return r;
}
__device__ __forceinline__ ull mul2(ull a, ull b) {
    ull r;
    asm("mul.rn.f32x2 %0, %1, %2;" : "=l"(r) : "l"(a), "l"(b));
    return r;
}
__device__ __forceinline__ ull add2(ull a, ull b) {
    ull r;
    asm("add.rn.f32x2 %0, %1, %2;" : "=l"(r) : "l"(a), "l"(b));
    return r;
}
__device__ __forceinline__ void upk2(ull v, float& lo, float& hi) {
    asm("mov.b64 {%0, %1}, %2;" : "=f"(lo), "=f"(hi) : "l"(v));
}
__device__ __forceinline__ float frcp(float x) {
    float r;
    asm("rcp.approx.f32 %0, %1;" : "=f"(r) : "f"(x));
    return r;
}
__host__ __device__ constexpr int IDX(int i, int j) {  // upper-tri 8x8, i<=j
    return i * 8 - i * (i - 1) / 2 + (j - i);
}

// 7 horizontal taps at one row-pair base; SUB subtracts (sign-flip 1st operand)
template<bool SUB>
__device__ __forceinline__ void tap7(const float* __restrict__ rp, ull A[60]) {
#pragma unroll
    for (int dx = 0; dx < 7; ++dx) {
        ull v[11];
#pragma unroll
        for (int ch = 0; ch < 11; ++ch)
            v[ch] = pk2(rp[ch * CH_STRIDE + dx],
                        rp[ch * CH_STRIDE + dx + SSTRIDE]);
        int k = 0;
#pragma unroll
        for (int i = 0; i < 8; ++i) {
            const ull si = SUB ? (v[i] ^ SGN2) : v[i];
#pragma unroll
            for (int j = i; j < 8; ++j) { ffma2(A[k], si, v[j]); ++k; }
#pragma unroll
            for (int c = 0; c < 3; ++c) ffma2(A[36 + i * 3 + c], si, v[8 + c]);
        }
    }
}

// ---- isolated solve: own register allocation (ABI call) --------------------
// slot[0..35]=AtA tri, slot[36..59]=AtY (read-only). cp = center features.
// op = &out[gy*IMW+gx]. Writes 3 channel pairs.
__device__ __noinline__ void solve_slot(const ull* __restrict__ slot,
                                        const float* __restrict__ cp,
                                        float* __restrict__ op)
{
    ull w[36];
#pragma unroll
    for (int m = 0; m < 36; ++m) w[m] = slot[m];
    const ull EPS2 = pk2(EPSR, EPSR);
#pragma unroll
    for (int i = 0; i < 8; ++i) w[IDX(i, i)] = add2(w[IDX(i, i)], EPS2);

    ull rhs[8];
#pragma unroll
    for (int ch = 0; ch < 8; ++ch)
        rhs[ch] = pk2(cp[ch * CH_STRIDE], cp[ch * CH_STRIDE + SSTRIDE]);

    // symmetric Gaussian elimination (SPD + Tikhonov; no pivoting)
#pragma unroll
    for (int k = 0; k < 8; ++k) {
        float dlo, dhi;
        upk2(w[IDX(k, k)], dlo, dhi);
        const ull ninv = pk2(-frcp(dlo), -frcp(dhi));
#pragma unroll
        for (int i = k + 1; i < 8; ++i) {
            const ull li = mul2(w[IDX(k, i)], ninv);     // -a_ki / d_k
            rhs[i] = ffma2g(li, rhs[k], rhs[i]);
#pragma unroll
            for (int j = i; j < 8; ++j)
                w[IDX(i, j)] = ffma2g(li, w[IDX(k, j)], w[IDX(i, j)]);
        }
    }
    ull nx[8];
#pragma unroll
    for (int i = 7; i >= 0; --i) {
        ull s = rhs[i];
#pragma unroll
        for (int j = 7; j > i; --j)
            s = ffma2g(w[IDX(i, j)], nx[j], s);
        float dlo, dhi;
        upk2(w[IDX(i, i)], dlo, dhi);
        nx[i] = mul2(s, pk2(-frcp(dlo), -frcp(dhi)));
    }

    // out_c = x . AtY_c = -(nx . AtY_c)
#pragma unroll
    for (int c = 0; c < 3; ++c) {
        ull a2 = 0ULL;
#pragma unroll
        for (int i = 0; i < 8; ++i)
            ffma2(a2, nx[i], slot[36 + i * 3 + c]);
        float olo, ohi;
        upk2(a2, olo, ohi);
        op[c * HW]       = -olo;
        op[c * HW + IMW] = -ohi;
    }
}

__global__ __launch_bounds__(128)
void ls_kernel(const float* __restrict__ inp,
               const float* __restrict__ dep,
               const float* __restrict__ alb,
               const float* __restrict__ nrm,
               float* __restrict__ out)
{
    extern __shared__ float SM[];
    float* S = SM;                          // S[ch][r][c], stride 22
    ull* X = (ull*)(SM + F_WORDS);          // stash: 128 slots x 61 ull

    const int tid = threadIdx.x;
    const int bx = blockIdx.x, by = blockIdx.y;
    const int gx0 = bx * TW - 3;
    const int gy0 = by * TH - 3;

    // ---- stage halo features (zeros outside image) ----
    for (int idx = tid; idx < HALO_H * HALO_W; idx += 128) {
        const int r = idx / HALO_W;
        const int c = idx - r * HALO_W;
        const int gy = gy0 + r;
        const int gx = gx0 + c;
        float v[11];
        if ((unsigned)gy < (unsigned)IMH && (unsigned)gx < (unsigned)IMW) {
            const int g = gy * IMW + gx;
            v[0] = 1.0f;
            v[1] = dep[g];
            v[2] = alb[g];  v[3] = alb[g + HW];  v[4] = alb[g + 2 * HW];
            v[5] = nrm[g];  v[6] = nrm[g + HW];  v[7] = nrm[g + 2 * HW];
            v[8] = inp[g];  v[9] = inp[g + HW];  v[10] = inp[g + 2 * HW];
        } else {
#pragma unroll
            for (int ch = 0; ch < 11; ++ch) v[ch] = 0.0f;
        }
#pragma unroll
        for (int ch = 0; ch < 11; ++ch)
            S[ch * CH_STRIDE + r * SSTRIDE + c] = v[ch];
    }
    __syncthreads();

    const int lx = tid & 15;
    const int ty = tid >> 4;                // 0..7
    const int lp0 = 4 * ty;                 // first output row (2 pairs: lp0, lp0+2)
    ull* xp = X + tid * XSTR;

    ull A[60];
#pragma unroll
    for (int m = 0; m < 60; ++m) A[m] = 0ULL;

    // ---- pair 0: full 49 taps ----
    {
        const float* b = &S[lp0 * SSTRIDE + lx];
#pragma unroll
        for (int dy = 0; dy < 7; ++dy)
            tap7<false>(b + dy * SSTRIDE, A);
    }

    // stash + isolated solve (A regs die across the call)
#pragma unroll
    for (int m = 0; m < 60; ++m) xp[m] = A[m];
    solve_slot(xp, &S[(lp0 + 3) * SSTRIDE + (lx + 3)],
               out + (by * TH + lp0) * IMW + bx * TW + lx);

    // restore A, slide 2 rows to pair 1
#pragma unroll
    for (int m = 0; m < 60; ++m) A[m] = xp[m];
    {
        const int lp = lp0 + 2;
        const float* b = &S[lp * SSTRIDE + lx];
        tap7<false>(b + 5 * SSTRIDE, A);
        tap7<false>(b + 6 * SSTRIDE, A);
        tap7<true >(b - 2 * SSTRIDE, A);
        tap7<true >(b - 1 * SSTRIDE, A);

#pragma unroll
        for (int m = 0; m < 60; ++m) xp[m] = A[m];
        solve_slot(xp, &S[(lp + 3) * SSTRIDE + (lx + 3)],
                   out + (by * TH + lp) * IMW + bx * TW + lx);
    }
}

extern "C" void kernel_launch(void* const* d_in, const int* in_sizes, int n_in,
                              void* d_out, int out_size) {
    const float* inp   = (const float*)d_in[0];
    const float* depth = (const float*)d_in[1];
    const float* alb   = (const float*)d_in[2];
    const float* nrm   = (const float*)d_in[3];
    float* out = (float*)d_out;

    cudaFuncSetAttribute(ls_kernel, cudaFuncAttributeMaxDynamicSharedMemorySize,
                         SMEM_BYTES);
    dim3 grid(IMW / TW, IMH / TH);   // (64, 32) = 2048 CTAs
    ls_kernel<<<grid, 128, SMEM_BYTES>>>(inp, depth, alb, nrm, out);
}